// round 12
// baseline (speedup 1.0000x reference)
#include <cuda_runtime.h>

#define TT   1024
#define BB   512
#define IND  64
#define HIDD 256
#define OUTD 32
#define TS   32
#define NT   (TT / TS)

typedef unsigned long long u64;

// Rounding contract (verified bitwise vs reference, rel_err 7.6e-8):
//  - dot products: single accumulator, ascending-k __fmaf_rn chain
//  - bias added after, separate __fadd_rn
//  - LIF: mem = __fmaf_rn(0.92, mem, cur) - reset (reset detached, prev mem)
//  - spike: (mem - 1.0f) > 0
// Bitwise-neutral exploits: fma.rn.f32x2 packs independent (t,t+1) chains;
// layer 2 = sparse ascending-k __fadd_rn sum over ballot-mask set bits (RR-4).
// Schedule: 4-deep software pipeline, ONE barrier per iteration:
//   iter i:  stage xq(i) | layer1(i-1) | layer2(i-2) | mem2+store(i-3)
// xq/msk/red double-buffered; within-iteration phases touch opposite parities.

__device__ __forceinline__ u64 ffma2(u64 a, u64 b, u64 c) {
    u64 d;
    asm("fma.rn.f32x2 %0, %1, %2, %3;" : "=l"(d) : "l"(a), "l"(b), "l"(c));
    return d;
}
__device__ __forceinline__ u64 dup2(float w) {
    u64 d;
    asm("mov.b64 %0, {%1, %1};" : "=l"(d) : "f"(w));
    return d;
}
__device__ __forceinline__ float lo2(u64 v) { return ((float2*)&v)->x; }
__device__ __forceinline__ float hi2(u64 v) { return ((float2*)&v)->y; }

// one round-robin step of a sparse chain: add selected weight or 0.0f
#define SPARSE_STEP(m, a, wp)                              \
    {                                                      \
        int ko = __ffs(m);                                 \
        int kk = (ko > 0) ? ko - 1 : 0;                    \
        float v = wp[kk * OUTD];                           \
        a = __fadd_rn(a, (ko > 0) ? v : 0.0f);             \
        m &= m - 1;                                        \
    }

__global__ void __launch_bounds__(256, 2) snn_kernel(
    const float* __restrict__ x,    // [T, B, IN]
    const float* __restrict__ W1,   // [HID, IN]
    const float* __restrict__ b1,   // [HID]
    const float* __restrict__ W2,   // [OUT, HID]
    const float* __restrict__ b2,   // [OUT]
    float* __restrict__ out)        // [2, T, B, OUT] (spk2 then mem2)
{
    __shared__ __align__(16) float2   xq[2][TS / 2][IND]; // dbuf (t,t+1) pairs, 16 KB
    __shared__ __align__(16) unsigned msk[2][TS][8];      // dbuf masks, 2 KB
    __shared__ __align__(16) float    w2s[HIDD][OUTD];    // W2^T, 32 KB
    __shared__ __align__(16) float    red[2][TS][OUTD];   // dbuf cur2, 8 KB

    const int b   = blockIdx.x;
    const int tid = threadIdx.x;   // layer 1: thread = hidden unit
    const int o   = tid & 31;
    const int tg  = tid >> 5;      // warp id; layer 2 t-group
    const int stp = tid >> 4;      // staging t-pair 0..15
    const int skc = tid & 15;      // staging chunk 0..15

    for (int e = tid; e < OUTD * HIDD; e += 256) {
        w2s[e % HIDD][e / HIDD] = W2[e];
    }

    float w1r[IND];
    #pragma unroll
    for (int k = 0; k < IND; k++) w1r[k] = W1[tid * IND + k];

    const float b1h = b1[tid];
    const float b2o = b2[o];
    float mem1 = 0.0f, mem2 = 0.0f;

    __syncthreads();   // w2s staged

    for (int i = 0; i < NT + 3; i++) {
        // ---- P0a) stage(i): issue x LDGs early (consumed after layer 1) ----
        float4 sa, sd;
        if (i < NT) {
            const int t0 = i * TS;
            sa = ((const float4*)(x + ((size_t)(t0 + 2 * stp)     * BB + b) * IND))[skc];
            sd = ((const float4*)(x + ((size_t)(t0 + 2 * stp + 1) * BB + b) * IND))[skc];
        }

        // ---- P3) mem2 + store for tile i-3 (warp 0; overlaps everything) ----
        if (i >= 3 && tg == 0) {
            const int pb  = (i - 3) & 1;
            const int t0p = (i - 3) * TS;
            #pragma unroll 4
            for (int t = 0; t < TS; t++) {
                float cur2 = red[pb][t][o];
                float r2 = (mem2 > 1.0f) ? 1.0f : 0.0f;
                mem2 = __fsub_rn(__fmaf_rn(0.92f, mem2, cur2), r2);
                float s2 = (__fsub_rn(mem2, 1.0f) > 0.0f) ? 1.0f : 0.0f;
                size_t idx = ((size_t)(t0p + t) * BB + b) * OUTD + o;
                out[idx] = s2;                              // spk2_rec
                out[(size_t)TT * BB * OUTD + idx] = mem2;   // mem2_rec
            }
        }

        // ---- P1) layer 1 for tile i-1: reads xq[(i-1)&1] -> msk[(i-1)&1] ----
        if (i >= 1 && i <= NT) {
            const int cb1 = (i - 1) & 1;
            #pragma unroll
            for (int s = 0; s < 2; s++) {          // t = 16s .. 16s+15
                const ulonglong2* r0 = (const ulonglong2*)xq[cb1][4 * s];
                const ulonglong2* r1 = (const ulonglong2*)xq[cb1][4 * s + 1];
                const ulonglong2* r2p = (const ulonglong2*)xq[cb1][4 * s + 2];
                const ulonglong2* r3 = (const ulonglong2*)xq[cb1][4 * s + 3];
                u64 acc0 = 0ull, acc1 = 0ull, acc2 = 0ull, acc3 = 0ull;
                #pragma unroll 8
                for (int kc = 0; kc < IND / 2; kc++) {
                    u64 wa = dup2(w1r[2 * kc]);
                    u64 wb = dup2(w1r[2 * kc + 1]);
                    ulonglong2 v0 = r0[kc];
                    ulonglong2 v1 = r1[kc];
                    ulonglong2 v2 = r2p[kc];
                    ulonglong2 v3 = r3[kc];
                    acc0 = ffma2(v0.x, wa, acc0);  acc0 = ffma2(v0.y, wb, acc0);
                    acc1 = ffma2(v1.x, wa, acc1);  acc1 = ffma2(v1.y, wb, acc1);
                    acc2 = ffma2(v2.x, wa, acc2);  acc2 = ffma2(v2.y, wb, acc2);
                    acc3 = ffma2(v3.x, wa, acc3);  acc3 = ffma2(v3.y, wb, acc3);
                }
                float c8[8] = {lo2(acc0), hi2(acc0), lo2(acc1), hi2(acc1),
                               lo2(acc2), hi2(acc2), lo2(acc3), hi2(acc3)};
                #pragma unroll
                for (int j = 0; j < 8; j++) {      // LIF ascending t
                    int t = 8 * s + j;
                    float cur1 = __fadd_rn(c8[j], b1h);
                    float r1f  = (mem1 > 1.0f) ? 1.0f : 0.0f;
                    mem1 = __fsub_rn(__fmaf_rn(0.92f, mem1, cur1), r1f);
                    unsigned bal = __ballot_sync(0xffffffffu,
                                       __fsub_rn(mem1, 1.0f) > 0.0f);
                    if (o == 0) msk[cb1][t][tg] = bal;
                }
            }
            // NOTE: pass s covers t-pairs 4s..4s+3 => t = 8s..8s+7; two passes
            // cover t-pairs 0..7 (t 0..15)?  t-pairs are 16 total: pairs
            // 4s..4s+3 for s=0,1 only covers 8 pairs. Handle remaining 8 pairs:
            #pragma unroll
            for (int s = 2; s < 4; s++) {
                const ulonglong2* r0 = (const ulonglong2*)xq[cb1][4 * s];
                const ulonglong2* r1 = (const ulonglong2*)xq[cb1][4 * s + 1];
                const ulonglong2* r2p = (const ulonglong2*)xq[cb1][4 * s + 2];
                const ulonglong2* r3 = (const ulonglong2*)xq[cb1][4 * s + 3];
                u64 acc0 = 0ull, acc1 = 0ull, acc2 = 0ull, acc3 = 0ull;
                #pragma unroll 8
                for (int kc = 0; kc < IND / 2; kc++) {
                    u64 wa = dup2(w1r[2 * kc]);
                    u64 wb = dup2(w1r[2 * kc + 1]);
                    ulonglong2 v0 = r0[kc];
                    ulonglong2 v1 = r1[kc];
                    ulonglong2 v2 = r2p[kc];
                    ulonglong2 v3 = r3[kc];
                    acc0 = ffma2(v0.x, wa, acc0);  acc0 = ffma2(v0.y, wb, acc0);
                    acc1 = ffma2(v1.x, wa, acc1);  acc1 = ffma2(v1.y, wb, acc1);
                    acc2 = ffma2(v2.x, wa, acc2);  acc2 = ffma2(v2.y, wb, acc2);
                    acc3 = ffma2(v3.x, wa, acc3);  acc3 = ffma2(v3.y, wb, acc3);
                }
                float c8[8] = {lo2(acc0), hi2(acc0), lo2(acc1), hi2(acc1),
                               lo2(acc2), hi2(acc2), lo2(acc3), hi2(acc3)};
                #pragma unroll
                for (int j = 0; j < 8; j++) {
                    int t = 8 * s + j;
                    float cur1 = __fadd_rn(c8[j], b1h);
                    float r1f  = (mem1 > 1.0f) ? 1.0f : 0.0f;
                    mem1 = __fsub_rn(__fmaf_rn(0.92f, mem1, cur1), r1f);
                    unsigned bal = __ballot_sync(0xffffffffu,
                                       __fsub_rn(mem1, 1.0f) > 0.0f);
                    if (o == 0) msk[cb1][t][tg] = bal;
                }
            }
        }

        // ---- P0b) stage(i): write xq[i&1] (consumers run next iteration) ----
        if (i < NT) {
            float4* q = (float4*)&xq[i & 1][stp][skc * 4];
            q[0] = make_float4(sa.x, sd.x, sa.y, sd.y);
            q[1] = make_float4(sa.z, sd.z, sa.w, sd.w);
        }

        // ---- P2) layer 2 for tile i-2: reads msk[(i-2)&1] -> red[(i-2)&1] ----
        if (i >= 2 && i <= NT + 1) {
            const int cb2 = (i - 2) & 1;
            float a0 = 0.0f, a1 = 0.0f, a2 = 0.0f, a3 = 0.0f;
            #pragma unroll
            for (int w = 0; w < 8; w++) {
                unsigned m0 = msk[cb2][tg][w];        // warp-uniform
                unsigned m1 = msk[cb2][tg + 8][w];
                unsigned m2 = msk[cb2][tg + 16][w];
                unsigned m3 = msk[cb2][tg + 24][w];
                const float* wp = &w2s[w * 32][o];
                while (m0 | m1 | m2 | m3) {           // uniform branch
                    SPARSE_STEP(m0, a0, wp)
                    SPARSE_STEP(m1, a1, wp)
                    SPARSE_STEP(m2, a2, wp)
                    SPARSE_STEP(m3, a3, wp)
                }
            }
            red[cb2][tg][o]      = __fadd_rn(a0, b2o);
            red[cb2][tg + 8][o]  = __fadd_rn(a1, b2o);
            red[cb2][tg + 16][o] = __fadd_rn(a2, b2o);
            red[cb2][tg + 24][o] = __fadd_rn(a3, b2o);
        }

        __syncthreads();   // single barrier: iteration i writes -> i+1 reads
    }
}

extern "C" void kernel_launch(void* const* d_in, const int* in_sizes, int n_in,
                              void* d_out, int out_size) {
    const float* x  = (const float*)d_in[0];  // spike_input [1024,512,64]
    const float* W1 = (const float*)d_in[1];  // [256,64]
    const float* b1 = (const float*)d_in[2];  // [256]
    const float* W2 = (const float*)d_in[3];  // [32,256]
    const float* b2 = (const float*)d_in[4];  // [32]
    float* out = (float*)d_out;               // 2*1024*512*32 floats

    snn_kernel<<<BB, 256>>>(x, W1, b1, W2, b2, out);
}

// round 13
// speedup vs baseline: 1.2153x; 1.2153x over previous
#include <cuda_runtime.h>

#define TT   1024
#define BB   512
#define IND  64
#define HIDD 256
#define OUTD 32
#define TS   32
#define NT   (TT / TS)

typedef unsigned long long u64;

// Rounding contract (verified bitwise vs reference, rel_err 7.6e-8):
//  - dot products: single accumulator, ascending-k __fmaf_rn chain
//  - bias added after, separate __fadd_rn
//  - LIF: mem = __fmaf_rn(0.92, mem, cur) - reset (reset detached, prev mem)
//  - spike: (mem - 1.0f) > 0
// Bitwise-neutral exploits: fma.rn.f32x2 packs independent (t,t+1) chains;
// layer 2 = sparse ascending-k __fadd_rn sum over ballot-mask set bits (RR-4).
// Occupancy play: W1 streamed from L2 (transposed by prep kernel into a
// __device__ global, coalesced LDG.64 per k-pair) instead of 64 registers.
// Single layer-1 pass with 16 t-pair accumulators -> ~58 regs -> 4 CTAs/SM,
// 8 warps/SMSP, all 512 CTAs resident in one wave.

__device__ float2 g_W1p[(IND / 2) * HIDD];   // [kc][h] = (W1[h][2kc], W1[h][2kc+1])

__global__ void prep_w1(const float* __restrict__ W1) {
    int kc = blockIdx.x;      // 0..31
    int h  = threadIdx.x;     // 0..255
    g_W1p[kc * HIDD + h] =
        make_float2(W1[h * IND + 2 * kc], W1[h * IND + 2 * kc + 1]);
}

__device__ __forceinline__ u64 ffma2(u64 a, u64 b, u64 c) {
    u64 d;
    asm("fma.rn.f32x2 %0, %1, %2, %3;" : "=l"(d) : "l"(a), "l"(b), "l"(c));
    return d;
}
__device__ __forceinline__ u64 dup2(float w) {
    u64 d;
    asm("mov.b64 %0, {%1, %1};" : "=l"(d) : "f"(w));
    return d;
}
__device__ __forceinline__ float lo2(u64 v) { return ((float2*)&v)->x; }
__device__ __forceinline__ float hi2(u64 v) { return ((float2*)&v)->y; }

// one round-robin step of a sparse chain: add selected weight or 0.0f
#define SPARSE_STEP(m, a, wp)                              \
    {                                                      \
        int ko = __ffs(m);                                 \
        int kk = (ko > 0) ? ko - 1 : 0;                    \
        float v = wp[kk * OUTD];                           \
        a = __fadd_rn(a, (ko > 0) ? v : 0.0f);             \
        m &= m - 1;                                        \
    }

__global__ void __launch_bounds__(256, 4) snn_kernel(
    const float* __restrict__ x,    // [T, B, IN]
    const float* __restrict__ b1,   // [HID]
    const float* __restrict__ W2,   // [OUT, HID]
    const float* __restrict__ b2,   // [OUT]
    float* __restrict__ out)        // [2, T, B, OUT] (spk2 then mem2)
{
    __shared__ __align__(16) float2   xq[TS / 2][IND];    // (t,t+1) pairs, 8 KB
    __shared__ __align__(16) unsigned msk[2][TS][8];      // dbuf masks, 2 KB
    __shared__ __align__(16) float    w2s[HIDD][OUTD];    // W2^T, 32 KB
    __shared__ __align__(16) float    red[2][TS][OUTD];   // dbuf cur2, 8 KB

    const int b   = blockIdx.x;
    const int tid = threadIdx.x;   // layer 1: thread = hidden unit
    const int o   = tid & 31;
    const int tg  = tid >> 5;      // warp id; layer 2 t-group
    const int stp = tid >> 4;      // staging t-pair 0..15
    const int skc = tid & 15;      // staging chunk 0..15

    for (int e = tid; e < OUTD * HIDD; e += 256) {
        w2s[e % HIDD][e / HIDD] = W2[e];
    }

    const float b1h = b1[tid];
    const float b2o = b2[o];
    float mem1 = 0.0f, mem2 = 0.0f;

    for (int tile = 0; tile <= NT; tile++) {
        const int cb = tile & 1;

        // ---- a) stage x tile as (t,t+1) interleaved pairs (R9 pattern) ----
        if (tile < NT) {
            const int t0 = tile * TS;
            float4 sa = ((const float4*)(x + ((size_t)(t0 + 2 * stp)     * BB + b) * IND))[skc];
            float4 sd = ((const float4*)(x + ((size_t)(t0 + 2 * stp + 1) * BB + b) * IND))[skc];
            float4* q = (float4*)&xq[stp][skc * 4];
            q[0] = make_float4(sa.x, sd.x, sa.y, sd.y);
            q[1] = make_float4(sa.z, sd.z, sa.w, sd.w);
        }
        __syncthreads();   // S_A: xq staged; red/msk handoff ordered

        // ---- b) layer 1: single pass, 16 t-pair accumulators,
        //         weights streamed from L2 with depth-1 prefetch ----
        if (tile < NT) {
            u64 acc[16];
            #pragma unroll
            for (int j = 0; j < 16; j++) acc[j] = 0ull;

            float2 wn = g_W1p[tid];            // kc = 0 prefetch
            #pragma unroll 4
            for (int kc = 0; kc < IND / 2; kc++) {
                float2 wc = wn;
                if (kc + 1 < IND / 2) wn = g_W1p[(kc + 1) * HIDD + tid];
                u64 wa = dup2(wc.x);
                u64 wb = dup2(wc.y);
                // column of x-pairs for k = 2kc, 2kc+1; rows 512 B apart
                const ulonglong2* col = (const ulonglong2*)&xq[0][2 * kc];
                #pragma unroll
                for (int tp = 0; tp < 16; tp++) {
                    ulonglong2 v = col[tp * (IND / 2)];
                    acc[tp] = ffma2(v.x, wa, acc[tp]);
                    acc[tp] = ffma2(v.y, wb, acc[tp]);
                }
            }

            // LIF ascending t over all 32 timesteps
            #pragma unroll
            for (int j = 0; j < 16; j++) {
                float cl = lo2(acc[j]);
                float ch = hi2(acc[j]);
                int   t  = 2 * j;
                float cur1 = __fadd_rn(cl, b1h);
                float r1f  = (mem1 > 1.0f) ? 1.0f : 0.0f;
                mem1 = __fsub_rn(__fmaf_rn(0.92f, mem1, cur1), r1f);
                unsigned bal = __ballot_sync(0xffffffffu,
                                   __fsub_rn(mem1, 1.0f) > 0.0f);
                if (o == 0) msk[cb][t][tg] = bal;
                cur1 = __fadd_rn(ch, b1h);
                r1f  = (mem1 > 1.0f) ? 1.0f : 0.0f;
                mem1 = __fsub_rn(__fmaf_rn(0.92f, mem1, cur1), r1f);
                bal = __ballot_sync(0xffffffffu,
                                   __fsub_rn(mem1, 1.0f) > 0.0f);
                if (o == 0) msk[cb][t + 1][tg] = bal;
            }
        }
        __syncthreads();   // S_B: msk[cb] ready

        // ---- c1) warp 0: mem2 recurrence + store for tile-1 ----
        if (tile > 0 && tg == 0) {
            const int pb  = (tile - 1) & 1;
            const int t0p = (tile - 1) * TS;
            #pragma unroll 4
            for (int t = 0; t < TS; t++) {
                float cur2 = red[pb][t][o];
                float r2 = (mem2 > 1.0f) ? 1.0f : 0.0f;
                mem2 = __fsub_rn(__fmaf_rn(0.92f, mem2, cur2), r2);
                float s2 = (__fsub_rn(mem2, 1.0f) > 0.0f) ? 1.0f : 0.0f;
                size_t idx = ((size_t)(t0p + t) * BB + b) * OUTD + o;
                out[idx] = s2;                              // spk2_rec
                out[(size_t)TT * BB * OUTD + idx] = mem2;   // mem2_rec
            }
        }

        // ---- c2) layer 2: 4 round-robined sparse chains -> red[cb] ----
        if (tile < NT) {
            float a0 = 0.0f, a1 = 0.0f, a2 = 0.0f, a3 = 0.0f;
            #pragma unroll
            for (int w = 0; w < 8; w++) {
                unsigned m0 = msk[cb][tg][w];        // warp-uniform
                unsigned m1 = msk[cb][tg + 8][w];
                unsigned m2 = msk[cb][tg + 16][w];
                unsigned m3 = msk[cb][tg + 24][w];
                const float* wp = &w2s[w * 32][o];
                while (m0 | m1 | m2 | m3) {          // uniform branch
                    SPARSE_STEP(m0, a0, wp)
                    SPARSE_STEP(m1, a1, wp)
                    SPARSE_STEP(m2, a2, wp)
                    SPARSE_STEP(m3, a3, wp)
                }
            }
            red[cb][tg][o]      = __fadd_rn(a0, b2o);
            red[cb][tg + 8][o]  = __fadd_rn(a1, b2o);
            red[cb][tg + 16][o] = __fadd_rn(a2, b2o);
            red[cb][tg + 24][o] = __fadd_rn(a3, b2o);
        }
        // no barrier here: next S_A orders red/msk handoff
    }
}

extern "C" void kernel_launch(void* const* d_in, const int* in_sizes, int n_in,
                              void* d_out, int out_size) {
    const float* x  = (const float*)d_in[0];  // spike_input [1024,512,64]
    const float* W1 = (const float*)d_in[1];  // [256,64]
    const float* b1 = (const float*)d_in[2];  // [256]
    const float* W2 = (const float*)d_in[3];  // [32,256]
    const float* b2 = (const float*)d_in[4];  // [32]
    float* out = (float*)d_out;               // 2*1024*512*32 floats

    prep_w1<<<IND / 2, HIDD>>>(W1);           // transpose W1 into g_W1p
    snn_kernel<<<BB, 256>>>(x, b1, W2, b2, out);
}

// round 14
// speedup vs baseline: 1.2164x; 1.0009x over previous
#include <cuda_runtime.h>

#define TT   1024
#define BB   512
#define IND  64
#define HIDD 256
#define OUTD 32
#define TS   32
#define NT   (TT / TS)

typedef unsigned long long u64;

// Rounding contract (verified bitwise vs reference, rel_err 7.6e-8):
//  - dot products: single accumulator, ascending-k __fmaf_rn chain
//  - bias added after, separate __fadd_rn
//  - LIF: mem = __fmaf_rn(0.92, mem, cur) - reset (reset detached, prev mem)
//  - spike: (mem - 1.0f) > 0
// Bitwise-neutral exploits: fma.rn.f32x2 packs independent (t,t+1) chains;
// layer 2 = sparse ascending-k __fadd_rn sum over ballot-mask set bits (RR-4).
// Occupancy play: W1 streamed from L2 (transposed by prep kernel into a
// __device__ global, coalesced LDG.64 per k-pair) instead of 64 registers.
// Single layer-1 pass with 16 t-pair accumulators -> ~58 regs -> 4 CTAs/SM,
// 8 warps/SMSP, all 512 CTAs resident in one wave.

__device__ float2 g_W1p[(IND / 2) * HIDD];   // [kc][h] = (W1[h][2kc], W1[h][2kc+1])

__global__ void prep_w1(const float* __restrict__ W1) {
    int kc = blockIdx.x;      // 0..31
    int h  = threadIdx.x;     // 0..255
    g_W1p[kc * HIDD + h] =
        make_float2(W1[h * IND + 2 * kc], W1[h * IND + 2 * kc + 1]);
}

__device__ __forceinline__ u64 ffma2(u64 a, u64 b, u64 c) {
    u64 d;
    asm("fma.rn.f32x2 %0, %1, %2, %3;" : "=l"(d) : "l"(a), "l"(b), "l"(c));
    return d;
}
__device__ __forceinline__ u64 dup2(float w) {
    u64 d;
    asm("mov.b64 %0, {%1, %1};" : "=l"(d) : "f"(w));
    return d;
}
__device__ __forceinline__ float lo2(u64 v) { return ((float2*)&v)->x; }
__device__ __forceinline__ float hi2(u64 v) { return ((float2*)&v)->y; }

// one round-robin step of a sparse chain: add selected weight or 0.0f
#define SPARSE_STEP(m, a, wp)                              \
    {                                                      \
        int ko = __ffs(m);                                 \
        int kk = (ko > 0) ? ko - 1 : 0;                    \
        float v = wp[kk * OUTD];                           \
        a = __fadd_rn(a, (ko > 0) ? v : 0.0f);             \
        m &= m - 1;                                        \
    }

__global__ void __launch_bounds__(256, 4) snn_kernel(
    const float* __restrict__ x,    // [T, B, IN]
    const float* __restrict__ b1,   // [HID]
    const float* __restrict__ W2,   // [OUT, HID]
    const float* __restrict__ b2,   // [OUT]
    float* __restrict__ out)        // [2, T, B, OUT] (spk2 then mem2)
{
    __shared__ __align__(16) float2   xq[TS / 2][IND];    // (t,t+1) pairs, 8 KB
    __shared__ __align__(16) unsigned msk[2][TS][8];      // dbuf masks, 2 KB
    __shared__ __align__(16) float    w2s[HIDD][OUTD];    // W2^T, 32 KB
    __shared__ __align__(16) float    red[2][TS][OUTD];   // dbuf cur2, 8 KB

    const int b   = blockIdx.x;
    const int tid = threadIdx.x;   // layer 1: thread = hidden unit
    const int o   = tid & 31;
    const int tg  = tid >> 5;      // warp id; layer 2 t-group
    const int stp = tid >> 4;      // staging t-pair 0..15
    const int skc = tid & 15;      // staging chunk 0..15

    for (int e = tid; e < OUTD * HIDD; e += 256) {
        w2s[e % HIDD][e / HIDD] = W2[e];
    }

    const float b1h = b1[tid];
    const float b2o = b2[o];
    float mem1 = 0.0f, mem2 = 0.0f;

    for (int tile = 0; tile <= NT; tile++) {
        const int cb = tile & 1;

        // ---- a) stage x tile as (t,t+1) interleaved pairs (R9 pattern) ----
        if (tile < NT) {
            const int t0 = tile * TS;
            float4 sa = ((const float4*)(x + ((size_t)(t0 + 2 * stp)     * BB + b) * IND))[skc];
            float4 sd = ((const float4*)(x + ((size_t)(t0 + 2 * stp + 1) * BB + b) * IND))[skc];
            float4* q = (float4*)&xq[stp][skc * 4];
            q[0] = make_float4(sa.x, sd.x, sa.y, sd.y);
            q[1] = make_float4(sa.z, sd.z, sa.w, sd.w);
        }
        __syncthreads();   // S_A: xq staged; red/msk handoff ordered

        // ---- b) layer 1: single pass, 16 t-pair accumulators,
        //         weights streamed from L2 with depth-1 prefetch ----
        if (tile < NT) {
            u64 acc[16];
            #pragma unroll
            for (int j = 0; j < 16; j++) acc[j] = 0ull;

            float2 wn = g_W1p[tid];            // kc = 0 prefetch
            #pragma unroll 4
            for (int kc = 0; kc < IND / 2; kc++) {
                float2 wc = wn;
                if (kc + 1 < IND / 2) wn = g_W1p[(kc + 1) * HIDD + tid];
                u64 wa = dup2(wc.x);
                u64 wb = dup2(wc.y);
                // column of x-pairs for k = 2kc, 2kc+1; rows 512 B apart
                const ulonglong2* col = (const ulonglong2*)&xq[0][2 * kc];
                #pragma unroll
                for (int tp = 0; tp < 16; tp++) {
                    ulonglong2 v = col[tp * (IND / 2)];
                    acc[tp] = ffma2(v.x, wa, acc[tp]);
                    acc[tp] = ffma2(v.y, wb, acc[tp]);
                }
            }

            // LIF ascending t over all 32 timesteps
            #pragma unroll
            for (int j = 0; j < 16; j++) {
                float cl = lo2(acc[j]);
                float ch = hi2(acc[j]);
                int   t  = 2 * j;
                float cur1 = __fadd_rn(cl, b1h);
                float r1f  = (mem1 > 1.0f) ? 1.0f : 0.0f;
                mem1 = __fsub_rn(__fmaf_rn(0.92f, mem1, cur1), r1f);
                unsigned bal = __ballot_sync(0xffffffffu,
                                   __fsub_rn(mem1, 1.0f) > 0.0f);
                if (o == 0) msk[cb][t][tg] = bal;
                cur1 = __fadd_rn(ch, b1h);
                r1f  = (mem1 > 1.0f) ? 1.0f : 0.0f;
                mem1 = __fsub_rn(__fmaf_rn(0.92f, mem1, cur1), r1f);
                bal = __ballot_sync(0xffffffffu,
                                   __fsub_rn(mem1, 1.0f) > 0.0f);
                if (o == 0) msk[cb][t + 1][tg] = bal;
            }
        }
        __syncthreads();   // S_B: msk[cb] ready

        // ---- c1) warp 0: mem2 recurrence + store for tile-1 ----
        if (tile > 0 && tg == 0) {
            const int pb  = (tile - 1) & 1;
            const int t0p = (tile - 1) * TS;
            #pragma unroll 4
            for (int t = 0; t < TS; t++) {
                float cur2 = red[pb][t][o];
                float r2 = (mem2 > 1.0f) ? 1.0f : 0.0f;
                mem2 = __fsub_rn(__fmaf_rn(0.92f, mem2, cur2), r2);
                float s2 = (__fsub_rn(mem2, 1.0f) > 0.0f) ? 1.0f : 0.0f;
                size_t idx = ((size_t)(t0p + t) * BB + b) * OUTD + o;
                out[idx] = s2;                              // spk2_rec
                out[(size_t)TT * BB * OUTD + idx] = mem2;   // mem2_rec
            }
        }

        // ---- c2) layer 2: 4 round-robined sparse chains -> red[cb] ----
        if (tile < NT) {
            float a0 = 0.0f, a1 = 0.0f, a2 = 0.0f, a3 = 0.0f;
            #pragma unroll
            for (int w = 0; w < 8; w++) {
                unsigned m0 = msk[cb][tg][w];        // warp-uniform
                unsigned m1 = msk[cb][tg + 8][w];
                unsigned m2 = msk[cb][tg + 16][w];
                unsigned m3 = msk[cb][tg + 24][w];
                const float* wp = &w2s[w * 32][o];
                while (m0 | m1 | m2 | m3) {          // uniform branch
                    SPARSE_STEP(m0, a0, wp)
                    SPARSE_STEP(m1, a1, wp)
                    SPARSE_STEP(m2, a2, wp)
                    SPARSE_STEP(m3, a3, wp)
                }
            }
            red[cb][tg][o]      = __fadd_rn(a0, b2o);
            red[cb][tg + 8][o]  = __fadd_rn(a1, b2o);
            red[cb][tg + 16][o] = __fadd_rn(a2, b2o);
            red[cb][tg + 24][o] = __fadd_rn(a3, b2o);
        }
        // no barrier here: next S_A orders red/msk handoff
    }
}

extern "C" void kernel_launch(void* const* d_in, const int* in_sizes, int n_in,
                              void* d_out, int out_size) {
    const float* x  = (const float*)d_in[0];  // spike_input [1024,512,64]
    const float* W1 = (const float*)d_in[1];  // [256,64]
    const float* b1 = (const float*)d_in[2];  // [256]
    const float* W2 = (const float*)d_in[3];  // [32,256]
    const float* b2 = (const float*)d_in[4];  // [32]
    float* out = (float*)d_out;               // 2*1024*512*32 floats

    prep_w1<<<IND / 2, HIDD>>>(W1);           // transpose W1 into g_W1p
    snn_kernel<<<BB, 256>>>(x, b1, W2, b2, out);
}

// round 15
// speedup vs baseline: 1.2177x; 1.0011x over previous
#include <cuda_runtime.h>

#define TT   1024
#define BB   512
#define IND  64
#define HIDD 256
#define OUTD 32
#define TS   32
#define NT   (TT / TS)

typedef unsigned long long u64;

// Rounding contract (verified bitwise vs reference, rel_err 7.6e-8):
//  - dot products: single accumulator, ascending-k __fmaf_rn chain
//  - bias added after, separate __fadd_rn
//  - LIF: mem = __fmaf_rn(0.92, mem, cur) - reset (reset detached, prev mem)
//  - spike: (mem - 1.0f) > 0
// Bitwise-neutral exploits: fma.rn.f32x2 packs independent (t,t+1) chains;
// layer 2 = sparse ascending-k __fadd_rn sum over ballot-mask set bits (RR-4).
// Occupancy play: W1 streamed from L2 (transposed by prep kernel into a
// __device__ global, coalesced LDG.64 per k-pair) instead of 64 registers.
// Single layer-1 pass with 16 t-pair accumulators -> ~58 regs -> 4 CTAs/SM,
// 8 warps/SMSP, all 512 CTAs resident in one wave.

__device__ float2 g_W1p[(IND / 2) * HIDD];   // [kc][h] = (W1[h][2kc], W1[h][2kc+1])

__global__ void prep_w1(const float* __restrict__ W1) {
    int kc = blockIdx.x;      // 0..31
    int h  = threadIdx.x;     // 0..255
    g_W1p[kc * HIDD + h] =
        make_float2(W1[h * IND + 2 * kc], W1[h * IND + 2 * kc + 1]);
}

__device__ __forceinline__ u64 ffma2(u64 a, u64 b, u64 c) {
    u64 d;
    asm("fma.rn.f32x2 %0, %1, %2, %3;" : "=l"(d) : "l"(a), "l"(b), "l"(c));
    return d;
}
__device__ __forceinline__ u64 dup2(float w) {
    u64 d;
    asm("mov.b64 %0, {%1, %1};" : "=l"(d) : "f"(w));
    return d;
}
__device__ __forceinline__ float lo2(u64 v) { return ((float2*)&v)->x; }
__device__ __forceinline__ float hi2(u64 v) { return ((float2*)&v)->y; }

// one round-robin step of a sparse chain: add selected weight or 0.0f
#define SPARSE_STEP(m, a, wp)                              \
    {                                                      \
        int ko = __ffs(m);                                 \
        int kk = (ko > 0) ? ko - 1 : 0;                    \
        float v = wp[kk * OUTD];                           \
        a = __fadd_rn(a, (ko > 0) ? v : 0.0f);             \
        m &= m - 1;                                        \
    }

__global__ void __launch_bounds__(256, 4) snn_kernel(
    const float* __restrict__ x,    // [T, B, IN]
    const float* __restrict__ b1,   // [HID]
    const float* __restrict__ W2,   // [OUT, HID]
    const float* __restrict__ b2,   // [OUT]
    float* __restrict__ out)        // [2, T, B, OUT] (spk2 then mem2)
{
    __shared__ __align__(16) float2   xq[TS / 2][IND];    // (t,t+1) pairs, 8 KB
    __shared__ __align__(16) unsigned msk[2][TS][8];      // dbuf masks, 2 KB
    __shared__ __align__(16) float    w2s[HIDD][OUTD];    // W2^T, 32 KB
    __shared__ __align__(16) float    red[2][TS][OUTD];   // dbuf cur2, 8 KB

    const int b   = blockIdx.x;
    const int tid = threadIdx.x;   // layer 1: thread = hidden unit
    const int o   = tid & 31;
    const int tg  = tid >> 5;      // warp id; layer 2 t-group
    const int stp = tid >> 4;      // staging t-pair 0..15
    const int skc = tid & 15;      // staging chunk 0..15

    for (int e = tid; e < OUTD * HIDD; e += 256) {
        w2s[e % HIDD][e / HIDD] = W2[e];
    }

    const float b1h = b1[tid];
    const float b2o = b2[o];
    float mem1 = 0.0f, mem2 = 0.0f;

    for (int tile = 0; tile <= NT; tile++) {
        const int cb = tile & 1;

        // ---- a) stage x tile as (t,t+1) interleaved pairs (R9 pattern) ----
        if (tile < NT) {
            const int t0 = tile * TS;
            float4 sa = ((const float4*)(x + ((size_t)(t0 + 2 * stp)     * BB + b) * IND))[skc];
            float4 sd = ((const float4*)(x + ((size_t)(t0 + 2 * stp + 1) * BB + b) * IND))[skc];
            float4* q = (float4*)&xq[stp][skc * 4];
            q[0] = make_float4(sa.x, sd.x, sa.y, sd.y);
            q[1] = make_float4(sa.z, sd.z, sa.w, sd.w);
        }
        __syncthreads();   // S_A: xq staged; red/msk handoff ordered

        // ---- b) layer 1: single pass, 16 t-pair accumulators,
        //         weights streamed from L2 with depth-1 prefetch ----
        if (tile < NT) {
            u64 acc[16];
            #pragma unroll
            for (int j = 0; j < 16; j++) acc[j] = 0ull;

            float2 wn = g_W1p[tid];            // kc = 0 prefetch
            #pragma unroll 4
            for (int kc = 0; kc < IND / 2; kc++) {
                float2 wc = wn;
                if (kc + 1 < IND / 2) wn = g_W1p[(kc + 1) * HIDD + tid];
                u64 wa = dup2(wc.x);
                u64 wb = dup2(wc.y);
                // column of x-pairs for k = 2kc, 2kc+1; rows 512 B apart
                const ulonglong2* col = (const ulonglong2*)&xq[0][2 * kc];
                #pragma unroll
                for (int tp = 0; tp < 16; tp++) {
                    ulonglong2 v = col[tp * (IND / 2)];
                    acc[tp] = ffma2(v.x, wa, acc[tp]);
                    acc[tp] = ffma2(v.y, wb, acc[tp]);
                }
            }

            // LIF ascending t over all 32 timesteps
            #pragma unroll
            for (int j = 0; j < 16; j++) {
                float cl = lo2(acc[j]);
                float ch = hi2(acc[j]);
                int   t  = 2 * j;
                float cur1 = __fadd_rn(cl, b1h);
                float r1f  = (mem1 > 1.0f) ? 1.0f : 0.0f;
                mem1 = __fsub_rn(__fmaf_rn(0.92f, mem1, cur1), r1f);
                unsigned bal = __ballot_sync(0xffffffffu,
                                   __fsub_rn(mem1, 1.0f) > 0.0f);
                if (o == 0) msk[cb][t][tg] = bal;
                cur1 = __fadd_rn(ch, b1h);
                r1f  = (mem1 > 1.0f) ? 1.0f : 0.0f;
                mem1 = __fsub_rn(__fmaf_rn(0.92f, mem1, cur1), r1f);
                bal = __ballot_sync(0xffffffffu,
                                   __fsub_rn(mem1, 1.0f) > 0.0f);
                if (o == 0) msk[cb][t + 1][tg] = bal;
            }
        }
        __syncthreads();   // S_B: msk[cb] ready

        // ---- c1) warp 0: mem2 recurrence + store for tile-1 ----
        if (tile > 0 && tg == 0) {
            const int pb  = (tile - 1) & 1;
            const int t0p = (tile - 1) * TS;
            #pragma unroll 4
            for (int t = 0; t < TS; t++) {
                float cur2 = red[pb][t][o];
                float r2 = (mem2 > 1.0f) ? 1.0f : 0.0f;
                mem2 = __fsub_rn(__fmaf_rn(0.92f, mem2, cur2), r2);
                float s2 = (__fsub_rn(mem2, 1.0f) > 0.0f) ? 1.0f : 0.0f;
                size_t idx = ((size_t)(t0p + t) * BB + b) * OUTD + o;
                out[idx] = s2;                              // spk2_rec
                out[(size_t)TT * BB * OUTD + idx] = mem2;   // mem2_rec
            }
        }

        // ---- c2) layer 2: 4 round-robined sparse chains -> red[cb] ----
        if (tile < NT) {
            float a0 = 0.0f, a1 = 0.0f, a2 = 0.0f, a3 = 0.0f;
            #pragma unroll
            for (int w = 0; w < 8; w++) {
                unsigned m0 = msk[cb][tg][w];        // warp-uniform
                unsigned m1 = msk[cb][tg + 8][w];
                unsigned m2 = msk[cb][tg + 16][w];
                unsigned m3 = msk[cb][tg + 24][w];
                const float* wp = &w2s[w * 32][o];
                while (m0 | m1 | m2 | m3) {          // uniform branch
                    SPARSE_STEP(m0, a0, wp)
                    SPARSE_STEP(m1, a1, wp)
                    SPARSE_STEP(m2, a2, wp)
                    SPARSE_STEP(m3, a3, wp)
                }
            }
            red[cb][tg][o]      = __fadd_rn(a0, b2o);
            red[cb][tg + 8][o]  = __fadd_rn(a1, b2o);
            red[cb][tg + 16][o] = __fadd_rn(a2, b2o);
            red[cb][tg + 24][o] = __fadd_rn(a3, b2o);
        }
        // no barrier here: next S_A orders red/msk handoff
    }
}

extern "C" void kernel_launch(void* const* d_in, const int* in_sizes, int n_in,
                              void* d_out, int out_size) {
    const float* x  = (const float*)d_in[0];  // spike_input [1024,512,64]
    const float* W1 = (const float*)d_in[1];  // [256,64]
    const float* b1 = (const float*)d_in[2];  // [256]
    const float* W2 = (const float*)d_in[3];  // [32,256]
    const float* b2 = (const float*)d_in[4];  // [32]
    float* out = (float*)d_out;               // 2*1024*512*32 floats

    prep_w1<<<IND / 2, HIDD>>>(W1);           // transpose W1 into g_W1p
    snn_kernel<<<BB, 256>>>(x, b1, W2, b2, out);
}